// round 8
// baseline (speedup 1.0000x reference)
#include <cuda_runtime.h>
#include <cuda_bf16.h>
#include <cstdint>
#include <cstring>

// ---------------------------------------------------------------------------
// SyntaxGCN: GCNConv(512->256) + relu + global_mean_pool + linear(256->1) + sigmoid
// GEMM on HMMA (mma.sync m16n8k16 bf16) with bf16x2 split:
//   x*W ~= xh*Wh + xh*Wl + xl*Wh   (fp32 accumulate, rel err ~1e-7)
// R8: 4-stage cp.async ring (TK=16, prefetch distance 3), one sync per iter.
// ---------------------------------------------------------------------------

constexpr int N_NODES  = 20000;
constexpr int N_EDGES  = 320000;
constexpr int IN_DIM   = 512;
constexpr int HID      = 256;
constexpr int HID4     = HID / 4;
constexpr int N_GRAPHS = 256;
constexpr int CSR_CAP  = 128;

constexpr int TILE_M = 128;
constexpr int TILE_N = 128;
constexpr int TK     = 16;
constexpr int NCHUNK = IN_DIM / TK;        // 32
constexpr int SSTR   = 24;                 // smem row stride in bf16 (48B, LDSM conflict-free)
constexpr int MAT    = TILE_M * SSTR;      // 3072
constexpr int STAGE  = 4 * MAT;            // 12288 bf16 = 24.6KB
constexpr int NSTAGE = 4;
constexpr int SMEM_BYTES = NSTAGE * STAGE * (int)sizeof(__nv_bfloat16);  // 98304

// Scratch (device globals)
__device__ float4 g_hs[N_NODES * HID4];
__device__ float  g_dinv[N_NODES];
__device__ int    g_cnt[N_NODES];
__device__ int    g_csr[N_NODES * CSR_CAP];
__device__ float4 g_pooled[N_GRAPHS * HID4];
__device__ float  g_counts[N_GRAPHS];
__device__ uint4  g_xhi[N_NODES * IN_DIM / 8];
__device__ uint4  g_xlo[N_NODES * IN_DIM / 8];
__device__ uint4  g_wthi[HID * IN_DIM / 8];   // transposed: [n][k]
__device__ uint4  g_wtlo[HID * IN_DIM / 8];

// ---------------- helpers ---------------------------------------------------
__device__ __forceinline__ void red_add_v4(float4* addr, float4 v) {
    asm volatile("red.global.add.v4.f32 [%0], {%1,%2,%3,%4};"
                 :: "l"(addr), "f"(v.x), "f"(v.y), "f"(v.z), "f"(v.w)
                 : "memory");
}

__device__ __forceinline__ uint32_t smem_u32(const void* p) {
    uint32_t a;
    asm("{ .reg .u64 t; cvta.to.shared.u64 t, %1; cvt.u32.u64 %0, t; }" : "=r"(a) : "l"(p));
    return a;
}

__device__ __forceinline__ void cp16(void* dst_smem, const void* src) {
    asm volatile("cp.async.ca.shared.global [%0], [%1], 16;"
                 :: "r"(smem_u32(dst_smem)), "l"(src) : "memory");
}

__device__ __forceinline__ void ldsm_x4(uint32_t* r, uint32_t addr) {
    asm volatile("ldmatrix.sync.aligned.m8n8.x4.shared.b16 {%0,%1,%2,%3}, [%4];"
                 : "=r"(r[0]), "=r"(r[1]), "=r"(r[2]), "=r"(r[3]) : "r"(addr));
}

__device__ __forceinline__ uint32_t pack_bf16x2(float a, float b) {
    __nv_bfloat162 h2 = __floats2bfloat162_rn(a, b);
    uint32_t u; memcpy(&u, &h2, 4);
    return u;
}

__device__ __forceinline__ void split2(float v0, float v1, uint32_t& hi, uint32_t& lo) {
    __nv_bfloat16 h0 = __float2bfloat16_rn(v0);
    __nv_bfloat16 h1 = __float2bfloat16_rn(v1);
    hi = pack_bf16x2(v0, v1);
    lo = pack_bf16x2(v0 - __bfloat162float(h0), v1 - __bfloat162float(h1));
}

__device__ __forceinline__ void mma_bf16(float* c, const uint32_t* a,
                                         uint32_t b0, uint32_t b1) {
    asm volatile(
        "mma.sync.aligned.m16n8k16.row.col.f32.bf16.bf16.f32 "
        "{%0,%1,%2,%3}, {%4,%5,%6,%7}, {%8,%9}, {%0,%1,%2,%3};"
        : "+f"(c[0]), "+f"(c[1]), "+f"(c[2]), "+f"(c[3])
        : "r"(a[0]), "r"(a[1]), "r"(a[2]), "r"(a[3]), "r"(b0), "r"(b1));
}

// --- init -------------------------------------------------------------------
__global__ void init_kernel() {
    int i = blockIdx.x * blockDim.x + threadIdx.x;
    if (i < N_GRAPHS * HID4) g_pooled[i] = make_float4(0.f, 0.f, 0.f, 0.f);
    if (i < N_GRAPHS)        g_counts[i] = 0.f;
    if (i < N_NODES)         g_cnt[i] = 0;
}

__global__ void edge_bin_kernel(const int* __restrict__ ei) {
    int e = blockIdx.x * blockDim.x + threadIdx.x;
    if (e >= N_EDGES) return;
    int src = __ldg(&ei[e]);
    int dst = __ldg(&ei[N_EDGES + e]);
    int pos = atomicAdd(&g_cnt[dst], 1);
    if (pos < CSR_CAP) g_csr[dst * CSR_CAP + pos] = src;
}

__global__ void dinv_kernel() {
    int n = blockIdx.x * blockDim.x + threadIdx.x;
    if (n < N_NODES) g_dinv[n] = rsqrtf((float)(g_cnt[n] + 1));
}

// --- preconvert x -> bf16 hi/lo --------------------------------------------
__global__ __launch_bounds__(256) void convert_x_kernel(const float4* __restrict__ X4) {
    int i = blockIdx.x * blockDim.x + threadIdx.x;
    if (i >= N_NODES * IN_DIM / 4) return;
    float4 v = X4[i];
    uint2 hi, lo;
    split2(v.x, v.y, hi.x, lo.x);
    split2(v.z, v.w, hi.y, lo.y);
    ((uint2*)g_xhi)[i] = hi;
    ((uint2*)g_xlo)[i] = lo;
}

// --- preconvert W -> transposed bf16 hi/lo [n][k] ---------------------------
__global__ __launch_bounds__(256) void convert_w_kernel(const float4* __restrict__ W4) {
    int i = blockIdx.x * blockDim.x + threadIdx.x;
    if (i >= IN_DIM * HID / 4) return;
    int k  = i >> 6;
    int n4 = i & 63;
    float4 v = W4[i];
    float f[4] = {v.x, v.y, v.z, v.w};
    __nv_bfloat16* wh = (__nv_bfloat16*)g_wthi;
    __nv_bfloat16* wl = (__nv_bfloat16*)g_wtlo;
    #pragma unroll
    for (int j = 0; j < 4; j++) {
        int n = n4 * 4 + j;
        __nv_bfloat16 h = __float2bfloat16_rn(f[j]);
        wh[(size_t)n * IN_DIM + k] = h;
        wl[(size_t)n * IN_DIM + k] = __float2bfloat16_rn(f[j] - __bfloat162float(h));
    }
}

// --- tensor-core GEMM: hs = (x @ W) * dinv[row] ----------------------------
// 256 threads, 8 warps (4m x 2n), warp tile 32x64, 4-stage cp.async ring.
__global__ __launch_bounds__(256, 2) void gemm_mma_kernel() {
    extern __shared__ __nv_bfloat16 sm[];
    const uint32_t smaddr = smem_u32(sm);

    const int tid  = threadIdx.x;
    const int lane = tid & 31;
    const int wid  = tid >> 5;
    const int warp_m = wid & 3;
    const int warp_n = wid >> 2;
    const int quad  = lane >> 2;
    const int tig   = lane & 3;

    const int m0 = blockIdx.y * TILE_M;
    const int n0 = blockIdx.x * TILE_N;

    const __nv_bfloat16* xh = (const __nv_bfloat16*)g_xhi;
    const __nv_bfloat16* xl = (const __nv_bfloat16*)g_xlo;
    const __nv_bfloat16* wh = (const __nv_bfloat16*)g_wthi;
    const __nv_bfloat16* wl = (const __nv_bfloat16*)g_wtlo;

    float acc[2][8][4];
    #pragma unroll
    for (int i = 0; i < 2; i++)
        #pragma unroll
        for (int j = 0; j < 8; j++)
            #pragma unroll
            for (int c = 0; c < 4; c++) acc[i][j][c] = 0.f;

    // ldmatrix per-lane address components (in bf16 elements)
    const int a_row = lane & 15;
    const int a_k   = (lane & 16) ? 8 : 0;
    const int a_base = (warp_m * 32 + a_row) * SSTR + a_k;
    const int b_row = ((lane >> 4) & 1) * 8 + (lane & 7);
    const int b_k   = (lane & 8) ? 8 : 0;
    const int b_base = (warp_n * 64 + b_row) * SSTR + b_k;

    // stage loader: 1024 x 16B cp.async (4 per thread: one per tile)
    const int l_row = tid >> 1;
    const int l_c   = tid & 1;
    int gr = m0 + l_row; if (gr >= N_NODES) gr = 0;
    const size_t aoff0 = (size_t)gr * IN_DIM + l_c * 8;
    const size_t boff0 = (size_t)(n0 + l_row) * IN_DIM + l_c * 8;
    const int doff = l_row * SSTR + l_c * 8;

    auto load_stage = [&](int s, int chunk) {
        const int k0 = chunk * TK;
        __nv_bfloat16* d = sm + s * STAGE + doff;
        cp16(d,           xh + aoff0 + k0);
        cp16(d + MAT,     xl + aoff0 + k0);
        cp16(d + 2 * MAT, wh + boff0 + k0);
        cp16(d + 3 * MAT, wl + boff0 + k0);
    };

    #pragma unroll
    for (int s = 0; s < NSTAGE - 1; s++) {
        load_stage(s, s);
        asm volatile("cp.async.commit_group;" ::: "memory");
    }

    for (int chunk = 0; chunk < NCHUNK; chunk++) {
        asm volatile("cp.async.wait_group 2;" ::: "memory");
        __syncthreads();

        // prefetch chunk+3 into ring slot (safe: all warps past compute of
        // the slot's previous occupant thanks to the sync above)
        if (chunk + NSTAGE - 1 < NCHUNK)
            load_stage((chunk + NSTAGE - 1) & (NSTAGE - 1), chunk + NSTAGE - 1);
        asm volatile("cp.async.commit_group;" ::: "memory");

        const uint32_t stg = smaddr + (uint32_t)(chunk & (NSTAGE - 1)) * (STAGE * 2);

        uint32_t ahi[2][4], alo[2][4];
        #pragma unroll
        for (int i = 0; i < 2; i++) {
            uint32_t aa = stg + (uint32_t)(a_base + i * 16 * SSTR) * 2;
            ldsm_x4(ahi[i], aa);
            ldsm_x4(alo[i], aa + MAT * 2);
        }
        #pragma unroll
        for (int p = 0; p < 4; p++) {
            uint32_t ba = stg + (uint32_t)(b_base + p * 16 * SSTR) * 2;
            uint32_t bh[4], bl[4];
            ldsm_x4(bh, ba + 2 * MAT * 2);
            ldsm_x4(bl, ba + 3 * MAT * 2);
            #pragma unroll
            for (int i = 0; i < 2; i++) {
                mma_bf16(acc[i][2 * p],     ahi[i], bh[0], bh[1]);  // xh*Wh
                mma_bf16(acc[i][2 * p],     ahi[i], bl[0], bl[1]);  // xh*Wl
                mma_bf16(acc[i][2 * p],     alo[i], bh[0], bh[1]);  // xl*Wh
                mma_bf16(acc[i][2 * p + 1], ahi[i], bh[2], bh[3]);
                mma_bf16(acc[i][2 * p + 1], ahi[i], bl[2], bl[3]);
                mma_bf16(acc[i][2 * p + 1], alo[i], bh[2], bh[3]);
            }
        }
    }

    // ---- epilogue: scale by dinv, store hs only --------------------------
    #pragma unroll
    for (int i = 0; i < 2; i++) {
        const int r0 = m0 + warp_m * 32 + i * 16 + quad;
        const int r1 = r0 + 8;
        const bool v0 = r0 < N_NODES;
        const bool v1 = r1 < N_NODES;
        const float d0 = v0 ? g_dinv[r0] : 0.f;
        const float d1 = v1 ? g_dinv[r1] : 0.f;
        #pragma unroll
        for (int j = 0; j < 8; j++) {
            const int col = n0 + warp_n * 64 + j * 8 + tig * 2;
            if (v0) {
                float2 s = make_float2(acc[i][j][0] * d0, acc[i][j][1] * d0);
                *(float2*)((float*)g_hs + (size_t)r0 * HID + col) = s;
            }
            if (v1) {
                float2 s = make_float2(acc[i][j][2] * d1, acc[i][j][3] * d1);
                *(float2*)((float*)g_hs + (size_t)r1 * HID + col) = s;
            }
        }
    }
}

// --- gather + relu + pool: one node per 64 threads --------------------------
__global__ __launch_bounds__(256) void gather_pool_kernel(
    const int* __restrict__ batch, const float* __restrict__ b)
{
    int t = blockIdx.x * blockDim.x + threadIdx.x;
    int n = t >> 6;
    int lane = t & 63;
    if (n >= N_NODES) return;

    int cnt = g_cnt[n];
    if (cnt > CSR_CAP) cnt = CSR_CAP;
    const int* lst = g_csr + n * CSR_CAP;

    float4 a = g_hs[(size_t)n * HID4 + lane];   // self loop
    int i = 0;
    for (; i + 4 <= cnt; i += 4) {
        int s0 = __ldg(&lst[i]);
        int s1 = __ldg(&lst[i + 1]);
        int s2 = __ldg(&lst[i + 2]);
        int s3 = __ldg(&lst[i + 3]);
        float4 v0 = __ldg(&g_hs[(size_t)s0 * HID4 + lane]);
        float4 v1 = __ldg(&g_hs[(size_t)s1 * HID4 + lane]);
        float4 v2 = __ldg(&g_hs[(size_t)s2 * HID4 + lane]);
        float4 v3 = __ldg(&g_hs[(size_t)s3 * HID4 + lane]);
        a.x += (v0.x + v1.x) + (v2.x + v3.x);
        a.y += (v0.y + v1.y) + (v2.y + v3.y);
        a.z += (v0.z + v1.z) + (v2.z + v3.z);
        a.w += (v0.w + v1.w) + (v2.w + v3.w);
    }
    for (; i < cnt; i++) {
        int s = __ldg(&lst[i]);
        float4 v = __ldg(&g_hs[(size_t)s * HID4 + lane]);
        a.x += v.x; a.y += v.y; a.z += v.z; a.w += v.w;
    }

    float d = g_dinv[n];
    float4 bb = __ldg((const float4*)b + lane);
    float4 v;
    v.x = fmaxf(fmaf(a.x, d, bb.x), 0.f);
    v.y = fmaxf(fmaf(a.y, d, bb.y), 0.f);
    v.z = fmaxf(fmaf(a.z, d, bb.z), 0.f);
    v.w = fmaxf(fmaf(a.w, d, bb.w), 0.f);

    int g = __ldg(&batch[n]);
    red_add_v4(&g_pooled[(size_t)g * HID4 + lane], v);
    if (lane == 0) atomicAdd(&g_counts[g], 1.f);
}

// --- head --------------------------------------------------------------------
__global__ void head_kernel(
    const float* __restrict__ lin_w, const float* __restrict__ lin_b,
    float* __restrict__ out)
{
    __shared__ float red[256];
    int g = blockIdx.x;
    int t = threadIdx.x;
    const float* pooled = (const float*)g_pooled;
    red[t] = pooled[g * HID + t] * __ldg(&lin_w[t]);
    __syncthreads();
    #pragma unroll
    for (int s = 128; s > 0; s >>= 1) {
        if (t < s) red[t] += red[t + s];
        __syncthreads();
    }
    if (t == 0) {
        float cnt = fmaxf(g_counts[g], 1.f);
        float z = red[0] / cnt + __ldg(&lin_b[0]);
        out[g] = 1.f / (1.f + expf(-z));
    }
}

// ---------------------------------------------------------------------------
extern "C" void kernel_launch(void* const* d_in, const int* in_sizes, int n_in,
                              void* d_out, int out_size) {
    const float* x     = (const float*)d_in[0];
    const int*   ei    = (const int*)d_in[1];
    const int*   batch = (const int*)d_in[2];
    const float* W     = (const float*)d_in[3];
    const float* b     = (const float*)d_in[4];
    const float* lin_w = (const float*)d_in[5];
    const float* lin_b = (const float*)d_in[6];
    float*       out   = (float*)d_out;

    static bool attr_set = false;
    if (!attr_set) {
        cudaFuncSetAttribute(gemm_mma_kernel,
                             cudaFuncAttributeMaxDynamicSharedMemorySize, SMEM_BYTES);
        attr_set = true;
    }

    init_kernel<<<(N_GRAPHS * HID + 255) / 256, 256>>>();
    edge_bin_kernel<<<(N_EDGES + 255) / 256, 256>>>(ei);
    dinv_kernel<<<(N_NODES + 255) / 256, 256>>>();
    convert_x_kernel<<<(N_NODES * IN_DIM / 4 + 255) / 256, 256>>>((const float4*)x);
    convert_w_kernel<<<(IN_DIM * HID / 4 + 255) / 256, 256>>>((const float4*)W);
    gemm_mma_kernel<<<dim3(HID / TILE_N, (N_NODES + TILE_M - 1) / TILE_M),
                      256, SMEM_BYTES>>>();
    gather_pool_kernel<<<(N_NODES * 64 + 255) / 256, 256>>>(batch, b);
    head_kernel<<<N_GRAPHS, 256>>>(lin_w, lin_b, out);
}

// round 9
// speedup vs baseline: 1.1260x; 1.1260x over previous
#include <cuda_runtime.h>
#include <cuda_bf16.h>
#include <cstdint>
#include <cstring>

// ---------------------------------------------------------------------------
// SyntaxGCN: GCNConv(512->256) + relu + global_mean_pool + linear(256->1) + sigmoid
// GEMM on HMMA (mma.sync m16n8k16 bf16) with bf16x2 split:
//   x*W ~= xh*Wh + xh*Wl + xl*Wh   (fp32 accumulate, rel err ~1e-7)
// R9: R7 structure (TK=32, 2-stage cp.async, ldmatrix) + MMA reorder to break
//     accumulator dependency chains + gather unroll-8 for MLP.
// ---------------------------------------------------------------------------

constexpr int N_NODES  = 20000;
constexpr int N_EDGES  = 320000;
constexpr int IN_DIM   = 512;
constexpr int HID      = 256;
constexpr int HID4     = HID / 4;
constexpr int N_GRAPHS = 256;
constexpr int CSR_CAP  = 128;

constexpr int TILE_M = 128;
constexpr int TILE_N = 128;
constexpr int TK     = 32;
constexpr int NCHUNK = IN_DIM / TK;        // 16
constexpr int SSTR   = 40;                 // smem row stride in bf16 (80B, LDSM conflict-free)
constexpr int MAT    = TILE_M * SSTR;
constexpr int STAGE  = 4 * MAT;
constexpr int SMEM_BYTES = 2 * STAGE * (int)sizeof(__nv_bfloat16);  // 81920

// Scratch (device globals)
__device__ float4 g_hs[N_NODES * HID4];
__device__ float  g_dinv[N_NODES];
__device__ int    g_cnt[N_NODES];
__device__ int    g_csr[N_NODES * CSR_CAP];
__device__ float4 g_pooled[N_GRAPHS * HID4];
__device__ float  g_counts[N_GRAPHS];
__device__ uint4  g_xhi[N_NODES * IN_DIM / 8];
__device__ uint4  g_xlo[N_NODES * IN_DIM / 8];
__device__ uint4  g_wthi[HID * IN_DIM / 8];   // transposed: [n][k]
__device__ uint4  g_wtlo[HID * IN_DIM / 8];

// ---------------- helpers ---------------------------------------------------
__device__ __forceinline__ void red_add_v4(float4* addr, float4 v) {
    asm volatile("red.global.add.v4.f32 [%0], {%1,%2,%3,%4};"
                 :: "l"(addr), "f"(v.x), "f"(v.y), "f"(v.z), "f"(v.w)
                 : "memory");
}

__device__ __forceinline__ uint32_t smem_u32(const void* p) {
    uint32_t a;
    asm("{ .reg .u64 t; cvta.to.shared.u64 t, %1; cvt.u32.u64 %0, t; }" : "=r"(a) : "l"(p));
    return a;
}

__device__ __forceinline__ void cp16(void* dst_smem, const void* src) {
    asm volatile("cp.async.ca.shared.global [%0], [%1], 16;"
                 :: "r"(smem_u32(dst_smem)), "l"(src) : "memory");
}

__device__ __forceinline__ void ldsm_x4(uint32_t* r, uint32_t addr) {
    asm volatile("ldmatrix.sync.aligned.m8n8.x4.shared.b16 {%0,%1,%2,%3}, [%4];"
                 : "=r"(r[0]), "=r"(r[1]), "=r"(r[2]), "=r"(r[3]) : "r"(addr));
}

__device__ __forceinline__ uint32_t pack_bf16x2(float a, float b) {
    __nv_bfloat162 h2 = __floats2bfloat162_rn(a, b);
    uint32_t u; memcpy(&u, &h2, 4);
    return u;
}

__device__ __forceinline__ void split2(float v0, float v1, uint32_t& hi, uint32_t& lo) {
    __nv_bfloat16 h0 = __float2bfloat16_rn(v0);
    __nv_bfloat16 h1 = __float2bfloat16_rn(v1);
    hi = pack_bf16x2(v0, v1);
    lo = pack_bf16x2(v0 - __bfloat162float(h0), v1 - __bfloat162float(h1));
}

__device__ __forceinline__ void mma_bf16(float* c, const uint32_t* a,
                                         uint32_t b0, uint32_t b1) {
    asm volatile(
        "mma.sync.aligned.m16n8k16.row.col.f32.bf16.bf16.f32 "
        "{%0,%1,%2,%3}, {%4,%5,%6,%7}, {%8,%9}, {%0,%1,%2,%3};"
        : "+f"(c[0]), "+f"(c[1]), "+f"(c[2]), "+f"(c[3])
        : "r"(a[0]), "r"(a[1]), "r"(a[2]), "r"(a[3]), "r"(b0), "r"(b1));
}

// --- init -------------------------------------------------------------------
__global__ void init_kernel() {
    int i = blockIdx.x * blockDim.x + threadIdx.x;
    if (i < N_GRAPHS * HID4) g_pooled[i] = make_float4(0.f, 0.f, 0.f, 0.f);
    if (i < N_GRAPHS)        g_counts[i] = 0.f;
    if (i < N_NODES)         g_cnt[i] = 0;
}

__global__ void edge_bin_kernel(const int* __restrict__ ei) {
    int e = blockIdx.x * blockDim.x + threadIdx.x;
    if (e >= N_EDGES) return;
    int src = __ldg(&ei[e]);
    int dst = __ldg(&ei[N_EDGES + e]);
    int pos = atomicAdd(&g_cnt[dst], 1);
    if (pos < CSR_CAP) g_csr[dst * CSR_CAP + pos] = src;
}

__global__ void dinv_kernel() {
    int n = blockIdx.x * blockDim.x + threadIdx.x;
    if (n < N_NODES) g_dinv[n] = rsqrtf((float)(g_cnt[n] + 1));
}

// --- preconvert x -> bf16 hi/lo --------------------------------------------
__global__ __launch_bounds__(256) void convert_x_kernel(const float4* __restrict__ X4) {
    int i = blockIdx.x * blockDim.x + threadIdx.x;
    if (i >= N_NODES * IN_DIM / 4) return;
    float4 v = X4[i];
    uint2 hi, lo;
    split2(v.x, v.y, hi.x, lo.x);
    split2(v.z, v.w, hi.y, lo.y);
    ((uint2*)g_xhi)[i] = hi;
    ((uint2*)g_xlo)[i] = lo;
}

// --- preconvert W -> transposed bf16 hi/lo [n][k] ---------------------------
__global__ __launch_bounds__(256) void convert_w_kernel(const float4* __restrict__ W4) {
    int i = blockIdx.x * blockDim.x + threadIdx.x;
    if (i >= IN_DIM * HID / 4) return;
    int k  = i >> 6;
    int n4 = i & 63;
    float4 v = W4[i];
    float f[4] = {v.x, v.y, v.z, v.w};
    __nv_bfloat16* wh = (__nv_bfloat16*)g_wthi;
    __nv_bfloat16* wl = (__nv_bfloat16*)g_wtlo;
    #pragma unroll
    for (int j = 0; j < 4; j++) {
        int n = n4 * 4 + j;
        __nv_bfloat16 h = __float2bfloat16_rn(f[j]);
        wh[(size_t)n * IN_DIM + k] = h;
        wl[(size_t)n * IN_DIM + k] = __float2bfloat16_rn(f[j] - __bfloat162float(h));
    }
}

// --- tensor-core GEMM: hs = (x @ W) * dinv[row] ----------------------------
// 256 threads, 8 warps (4m x 2n), warp tile 32x64, ldmatrix fragment loads.
__global__ __launch_bounds__(256, 2) void gemm_mma_kernel() {
    extern __shared__ __nv_bfloat16 sm[];
    const uint32_t smaddr = smem_u32(sm);

    const int tid  = threadIdx.x;
    const int lane = tid & 31;
    const int wid  = tid >> 5;
    const int warp_m = wid & 3;
    const int warp_n = wid >> 2;
    const int quad  = lane >> 2;
    const int tig   = lane & 3;

    const int m0 = blockIdx.y * TILE_M;
    const int n0 = blockIdx.x * TILE_N;

    const __nv_bfloat16* xh = (const __nv_bfloat16*)g_xhi;
    const __nv_bfloat16* xl = (const __nv_bfloat16*)g_xlo;
    const __nv_bfloat16* wh = (const __nv_bfloat16*)g_wthi;
    const __nv_bfloat16* wl = (const __nv_bfloat16*)g_wtlo;

    float acc[2][8][4];
    #pragma unroll
    for (int i = 0; i < 2; i++)
        #pragma unroll
        for (int j = 0; j < 8; j++)
            #pragma unroll
            for (int c = 0; c < 4; c++) acc[i][j][c] = 0.f;

    // ldmatrix per-lane address components (in bf16 elements)
    const int a_row = lane & 15;
    const int a_k   = (lane & 16) ? 8 : 0;
    const int a_base = (warp_m * 32 + a_row) * SSTR + a_k;
    const int b_row = ((lane >> 4) & 1) * 8 + (lane & 7);
    const int b_k   = (lane & 8) ? 8 : 0;
    const int b_base = (warp_n * 64 + b_row) * SSTR + b_k;

    auto load_stage = [&](int s, int chunk) {
        const int k0 = chunk * TK;
        __nv_bfloat16* st = sm + s * STAGE;
        #pragma unroll
        for (int r = 0; r < 2; r++) {
            int idx = tid + 256 * r;
            int row = idx >> 2;
            int c   = idx & 3;
            int gr  = m0 + row; if (gr >= N_NODES) gr = 0;
            size_t aoff = (size_t)gr * IN_DIM + k0 + c * 8;
            size_t boff = (size_t)(n0 + row) * IN_DIM + k0 + c * 8;
            __nv_bfloat16* d = st + row * SSTR + c * 8;
            cp16(d,           xh + aoff);
            cp16(d + MAT,     xl + aoff);
            cp16(d + 2 * MAT, wh + boff);
            cp16(d + 3 * MAT, wl + boff);
        }
    };

    load_stage(0, 0);
    asm volatile("cp.async.commit_group;" ::: "memory");

    for (int chunk = 0; chunk < NCHUNK; chunk++) {
        if (chunk + 1 < NCHUNK) load_stage((chunk + 1) & 1, chunk + 1);
        asm volatile("cp.async.commit_group;" ::: "memory");
        asm volatile("cp.async.wait_group 1;" ::: "memory");
        __syncthreads();

        const uint32_t stg = smaddr + (uint32_t)(chunk & 1) * (STAGE * 2);

        #pragma unroll
        for (int ks = 0; ks < 2; ks++) {
            const int kb = ks * 16;
            uint32_t ahi[2][4], alo[2][4];
            #pragma unroll
            for (int i = 0; i < 2; i++) {
                uint32_t aa = stg + (uint32_t)(a_base + i * 16 * SSTR + kb) * 2;
                ldsm_x4(ahi[i], aa);
                ldsm_x4(alo[i], aa + MAT * 2);
            }
            #pragma unroll
            for (int p = 0; p < 4; p++) {
                uint32_t ba = stg + (uint32_t)(b_base + p * 16 * SSTR + kb) * 2;
                uint32_t bh[4], bl[4];
                ldsm_x4(bh, ba + 2 * MAT * 2);
                ldsm_x4(bl, ba + 3 * MAT * 2);
                // pass-major order: 4 independent accs per pass, so same-acc
                // reuse distance is 4 MMAs (was 1 -> serial 3-chain).
                mma_bf16(acc[0][2 * p],     ahi[0], bh[0], bh[1]);   // xh*Wh
                mma_bf16(acc[1][2 * p],     ahi[1], bh[0], bh[1]);
                mma_bf16(acc[0][2 * p + 1], ahi[0], bh[2], bh[3]);
                mma_bf16(acc[1][2 * p + 1], ahi[1], bh[2], bh[3]);
                mma_bf16(acc[0][2 * p],     ahi[0], bl[0], bl[1]);   // xh*Wl
                mma_bf16(acc[1][2 * p],     ahi[1], bl[0], bl[1]);
                mma_bf16(acc[0][2 * p + 1], ahi[0], bl[2], bl[3]);
                mma_bf16(acc[1][2 * p + 1], ahi[1], bl[2], bl[3]);
                mma_bf16(acc[0][2 * p],     alo[0], bh[0], bh[1]);   // xl*Wh
                mma_bf16(acc[1][2 * p],     alo[1], bh[0], bh[1]);
                mma_bf16(acc[0][2 * p + 1], alo[0], bh[2], bh[3]);
                mma_bf16(acc[1][2 * p + 1], alo[1], bh[2], bh[3]);
            }
        }
        __syncthreads();
    }

    // ---- epilogue: scale by dinv, store hs only --------------------------
    #pragma unroll
    for (int i = 0; i < 2; i++) {
        const int r0 = m0 + warp_m * 32 + i * 16 + quad;
        const int r1 = r0 + 8;
        const bool v0 = r0 < N_NODES;
        const bool v1 = r1 < N_NODES;
        const float d0 = v0 ? g_dinv[r0] : 0.f;
        const float d1 = v1 ? g_dinv[r1] : 0.f;
        #pragma unroll
        for (int j = 0; j < 8; j++) {
            const int col = n0 + warp_n * 64 + j * 8 + tig * 2;
            if (v0) {
                float2 s = make_float2(acc[i][j][0] * d0, acc[i][j][1] * d0);
                *(float2*)((float*)g_hs + (size_t)r0 * HID + col) = s;
            }
            if (v1) {
                float2 s = make_float2(acc[i][j][2] * d1, acc[i][j][3] * d1);
                *(float2*)((float*)g_hs + (size_t)r1 * HID + col) = s;
            }
        }
    }
}

// --- gather + relu + pool: one node per 64 threads, unroll 8 ----------------
__global__ __launch_bounds__(256) void gather_pool_kernel(
    const int* __restrict__ batch, const float* __restrict__ b)
{
    int t = blockIdx.x * blockDim.x + threadIdx.x;
    int n = t >> 6;
    int lane = t & 63;
    if (n >= N_NODES) return;

    int cnt = g_cnt[n];
    if (cnt > CSR_CAP) cnt = CSR_CAP;
    const int* lst = g_csr + n * CSR_CAP;

    float4 a = g_hs[(size_t)n * HID4 + lane];   // self loop
    int i = 0;
    for (; i + 8 <= cnt; i += 8) {
        int s[8];
        #pragma unroll
        for (int q = 0; q < 8; q++) s[q] = __ldg(&lst[i + q]);
        float4 v[8];
        #pragma unroll
        for (int q = 0; q < 8; q++) v[q] = __ldg(&g_hs[(size_t)s[q] * HID4 + lane]);
        #pragma unroll
        for (int q = 0; q < 8; q++) {
            a.x += v[q].x; a.y += v[q].y; a.z += v[q].z; a.w += v[q].w;
        }
    }
    for (; i + 4 <= cnt; i += 4) {
        int s[4];
        #pragma unroll
        for (int q = 0; q < 4; q++) s[q] = __ldg(&lst[i + q]);
        float4 v[4];
        #pragma unroll
        for (int q = 0; q < 4; q++) v[q] = __ldg(&g_hs[(size_t)s[q] * HID4 + lane]);
        #pragma unroll
        for (int q = 0; q < 4; q++) {
            a.x += v[q].x; a.y += v[q].y; a.z += v[q].z; a.w += v[q].w;
        }
    }
    for (; i < cnt; i++) {
        int s = __ldg(&lst[i]);
        float4 v = __ldg(&g_hs[(size_t)s * HID4 + lane]);
        a.x += v.x; a.y += v.y; a.z += v.z; a.w += v.w;
    }

    float d = g_dinv[n];
    float4 bb = __ldg((const float4*)b + lane);
    float4 v;
    v.x = fmaxf(fmaf(a.x, d, bb.x), 0.f);
    v.y = fmaxf(fmaf(a.y, d, bb.y), 0.f);
    v.z = fmaxf(fmaf(a.z, d, bb.z), 0.f);
    v.w = fmaxf(fmaf(a.w, d, bb.w), 0.f);

    int g = __ldg(&batch[n]);
    red_add_v4(&g_pooled[(size_t)g * HID4 + lane], v);
    if (lane == 0) atomicAdd(&g_counts[g], 1.f);
}

// --- head --------------------------------------------------------------------
__global__ void head_kernel(
    const float* __restrict__ lin_w, const float* __restrict__ lin_b,
    float* __restrict__ out)
{
    __shared__ float red[256];
    int g = blockIdx.x;
    int t = threadIdx.x;
    const float* pooled = (const float*)g_pooled;
    red[t] = pooled[g * HID + t] * __ldg(&lin_w[t]);
    __syncthreads();
    #pragma unroll
    for (int s = 128; s > 0; s >>= 1) {
        if (t < s) red[t] += red[t + s];
        __syncthreads();
    }
    if (t == 0) {
        float cnt = fmaxf(g_counts[g], 1.f);
        float z = red[0] / cnt + __ldg(&lin_b[0]);
        out[g] = 1.f / (1.f + expf(-z));
    }
}

// ---------------------------------------------------------------------------
extern "C" void kernel_launch(void* const* d_in, const int* in_sizes, int n_in,
                              void* d_out, int out_size) {
    const float* x     = (const float*)d_in[0];
    const int*   ei    = (const int*)d_in[1];
    const int*   batch = (const int*)d_in[2];
    const float* W     = (const float*)d_in[3];
    const float* b     = (const float*)d_in[4];
    const float* lin_w = (const float*)d_in[5];
    const float* lin_b = (const float*)d_in[6];
    float*       out   = (float*)d_out;

    static bool attr_set = false;
    if (!attr_set) {
        cudaFuncSetAttribute(gemm_mma_kernel,
                             cudaFuncAttributeMaxDynamicSharedMemorySize, SMEM_BYTES);
        attr_set = true;
    }

    init_kernel<<<(N_GRAPHS * HID + 255) / 256, 256>>>();
    edge_bin_kernel<<<(N_EDGES + 255) / 256, 256>>>(ei);
    dinv_kernel<<<(N_NODES + 255) / 256, 256>>>();
    convert_x_kernel<<<(N_NODES * IN_DIM / 4 + 255) / 256, 256>>>((const float4*)x);
    convert_w_kernel<<<(IN_DIM * HID / 4 + 255) / 256, 256>>>((const float4*)W);
    gemm_mma_kernel<<<dim3(HID / TILE_N, (N_NODES + TILE_M - 1) / TILE_M),
                      256, SMEM_BYTES>>>();
    gather_pool_kernel<<<(N_NODES * 64 + 255) / 256, 256>>>(batch, b);
    head_kernel<<<N_GRAPHS, 256>>>(lin_w, lin_b, out);
}